// round 12
// baseline (speedup 1.0000x reference)
#include <cuda_runtime.h>
#include <cuda_fp16.h>
#include <cstdint>

// ---------------------------------------------------------------------------
// TFN forward. R12: base = R9 (best, 97.0us). Main kernel k-padding removed:
// rows 0-95 via 6 k16 HMMA steps (was 7 with 15 zero rows = 13.4% wasted
// HMMA on a pipe-rate-bound kernel), row 96 via fp32 rank-1 update (6 LDS.32
// + 24 FFMA per thread per chunk). No zero-pad rows; smem ring 70->60.5 KB.
// ---------------------------------------------------------------------------

#define NBLK   152
#define BDIM   64
#define HDIM   96
#define LDH    104            // smem B row stride in halfs (208 B, LDSM conflict-free)
#define KROWS  97             // exactly the data rows; no padding
#define WBUFH  (KROWS * LDH)  // halfs per stage buffer
#define SMEM_BYTES (3*WBUFH*2 + 2*6208*4)

__device__ float g_a1[BDIM * 97];
__device__ float g_v1[BDIM * 97];
__device__ float g_t1[BDIM * 97];
__device__ float g_part[NBLK * BDIM * HDIM];

// ---------------------------------------------------------------------------

__device__ __forceinline__ uint32_t h2u(__half2 h) {
    return *reinterpret_cast<uint32_t*>(&h);
}

__device__ __forceinline__ void mma_f16(float c[4],
                                        uint32_t a0, uint32_t a1,
                                        uint32_t a2, uint32_t a3,
                                        uint32_t b0, uint32_t b1) {
    asm volatile(
        "mma.sync.aligned.m16n8k16.row.col.f32.f16.f16.f32 "
        "{%0,%1,%2,%3}, {%4,%5,%6,%7}, {%8,%9}, {%0,%1,%2,%3};"
        : "+f"(c[0]), "+f"(c[1]), "+f"(c[2]), "+f"(c[3])
        : "r"(a0), "r"(a1), "r"(a2), "r"(a3), "r"(b0), "r"(b1));
}

struct __align__(8) H4 { __half2 a, b; };

// 97*96 = 9312 floats = 2328 float4 per chunk. 256 threads: 9 each + 24 extra.
__device__ __forceinline__ void stage_ldg(float4 (&stg)[10],
                                          const float* __restrict__ W1,
                                          int av, int tid) {
    const float4* src = reinterpret_cast<const float4*>(W1 + (size_t)av * 9312);
#pragma unroll
    for (int j = 0; j < 9; j++) stg[j] = src[tid + j * 256];
    if (tid < 24) stg[9] = src[2304 + tid];
}

__device__ __forceinline__ void cvt_store(__half* buf, int q, float4 v) {
    int e = q * 4;
    int t = e / 96;
    int c = e - t * 96;
    H4 o;
    o.a = __floats2half2_rn(v.x, v.y);
    o.b = __floats2half2_rn(v.z, v.w);
    *reinterpret_cast<H4*>(buf + t * LDH + c) = o;
}

__device__ __forceinline__ void stage_sts(__half* buf, const float4 (&stg)[10],
                                          int tid) {
#pragma unroll
    for (int j = 0; j < 9; j++) cvt_store(buf, tid + j * 256, stg[j]);
    if (tid < 24) cvt_store(buf, 2304 + tid, stg[9]);
}

// ---------------------------------------------------------------------------
// Kernel 1: encoders. grid (64 batch, 3 mods), 768 threads = 96 h x 8 slices.
// ---------------------------------------------------------------------------
__global__ void __launch_bounds__(768) tfn_enc(
    const float* __restrict__ audios, const float* __restrict__ texts,
    const float* __restrict__ videos,
    const float* __restrict__ Wa, const float* __restrict__ ba,
    const float* __restrict__ Wt, const float* __restrict__ bt,
    const float* __restrict__ Wv, const float* __restrict__ bv) {
    const int b   = blockIdx.x;
    const int mod = blockIdx.y;
    const int tid = threadIdx.x;

    const float* x; const float* W; const float* bias; float* out; int K;
    if (mod == 0)      { x = audios; W = Wa; bias = ba; out = g_a1; K = 512; }
    else if (mod == 1) { x = texts;  W = Wt; bias = bt; out = g_t1; K = 1024; }
    else               { x = videos; W = Wv; bias = bv; out = g_v1; K = 512; }

    __shared__ float xs[1024];
    __shared__ float ps[768];

    const float* xb = x + (size_t)b * K;
    for (int i = tid; i < K; i += 768) xs[i] = xb[i];
    __syncthreads();

    const int h  = tid % 96;
    const int g  = tid / 96;           // 0..7
    const int kq = K >> 3;             // 64 or 128
    const int k0 = g * kq;

    float acc = 0.f;
#pragma unroll 8
    for (int k = k0; k < k0 + kq; k++)
        acc += xs[k] * W[k * HDIM + h];
    ps[tid] = acc;
    __syncthreads();

    if (g == 0) {
        float r = bias[h];
#pragma unroll
        for (int i = 0; i < 8; i++) r += ps[h + 96 * i];
        out[b * 97 + 1 + h] = fmaxf(r, 0.f);
        if (h == 0) out[b * 97] = 1.f;
    }
}

// ---------------------------------------------------------------------------
// Kernel 2: main fused trilinear GEMM (y1 partials, pre-bias/relu)
//   152 CTAs x 256 threads, 1 CTA/SM, prefetch distance 3, warp grid 4m x 2n
//   6 k16 HMMA steps (rows 0-95) + fp32 rank-1 update for row 96.
// ---------------------------------------------------------------------------
__global__ void __launch_bounds__(256, 1) tfn_main(const float* __restrict__ W1) {
    extern __shared__ char smx[];
    __half* wb0 = reinterpret_cast<__half*>(smx);
    __half* wb1 = wb0 + WBUFH;
    __half* wb2 = wb1 + WBUFH;
    float*  a1s = reinterpret_cast<float*>(wb2 + WBUFH);
    float*  v1s = a1s + 6208;

    const int tid  = threadIdx.x;
    const int lane = tid & 31;
    const int wid  = tid >> 5;
    const int wm   = wid & 3;    // m-warp: batch rows 16*wm..16*wm+15
    const int wn   = wid >> 2;   // n-warp: cols 48*wn..48*wn+47
    const int gid  = lane >> 2;
    const int tig  = lane & 3;
    const int b0   = wm * 16 + gid;
    const int nbase = wn * 48;

    for (int i = tid; i < 6208; i += 256) { a1s[i] = g_a1[i]; v1s[i] = g_v1[i]; }

    // persistent t1 A-fragments as half2 pairs: 6 k16-steps (rows 0..95)
    __half2 t1f[6][4];
#pragma unroll
    for (int ks = 0; ks < 6; ks++) {
        int ka = ks * 16 + 2 * tig;     // <= 86
        int kb = ka + 8;                // <= 94
        t1f[ks][0] = __floats2half2_rn(g_t1[b0 * 97 + ka], g_t1[b0 * 97 + ka + 1]);
        t1f[ks][1] = __floats2half2_rn(g_t1[(b0 + 8) * 97 + ka], g_t1[(b0 + 8) * 97 + ka + 1]);
        t1f[ks][2] = __floats2half2_rn(g_t1[b0 * 97 + kb], g_t1[b0 * 97 + kb + 1]);
        t1f[ks][3] = __floats2half2_rn(g_t1[(b0 + 8) * 97 + kb], g_t1[(b0 + 8) * 97 + kb + 1]);
    }
    // row-96 t1 values (fp32)
    const float t96a = g_t1[b0 * 97 + 96];
    const float t96b = g_t1[(b0 + 8) * 97 + 96];

    float Y[6][4];
#pragma unroll
    for (int j = 0; j < 6; j++) { Y[j][0] = Y[j][1] = Y[j][2] = Y[j][3] = 0.f; }

    const int bk = blockIdx.x;
    // 9409 = 152*61 + 137 : first 137 blocks take 62 chunks
    const int cstart = (bk < 137) ? bk * 62 : bk * 61 + 137;
    const int ccnt   = (bk < 137) ? 62 : 61;

    const int lrow = lane & 15;          // k row within k16 step
    const int lcol = (lane >> 4) * 8;    // 0 or 8 within n16 block

    auto compute = [&](int av, const __half* curb) {
        const int ca = av / 97;
        const int cv = av - ca * 97;
        const float m0 = a1s[b0 * 97 + ca] * v1s[b0 * 97 + cv];
        const float m1 = a1s[(b0 + 8) * 97 + ca] * v1s[(b0 + 8) * 97 + cv];
        const __half2 m0h = __float2half2_rn(m0);
        const __half2 m1h = __float2half2_rn(m1);
#pragma unroll
        for (int ks = 0; ks < 6; ks++) {
            const uint32_t A0 = h2u(__hmul2(m0h, t1f[ks][0]));
            const uint32_t A1 = h2u(__hmul2(m1h, t1f[ks][1]));
            const uint32_t A2 = h2u(__hmul2(m0h, t1f[ks][2]));
            const uint32_t A3 = h2u(__hmul2(m1h, t1f[ks][3]));
            const __half* rowp = curb + (ks * 16 + lrow) * LDH + nbase + lcol;
#pragma unroll
            for (int j3 = 0; j3 < 3; j3++) {
                uint32_t saddr =
                    (uint32_t)__cvta_generic_to_shared(rowp + 16 * j3);
                uint32_t B0, B1, B2, B3;
                asm volatile(
                    "ldmatrix.sync.aligned.m8n8.x4.trans.shared.b16 "
                    "{%0,%1,%2,%3}, [%4];"
                    : "=r"(B0), "=r"(B1), "=r"(B2), "=r"(B3) : "r"(saddr));
                mma_f16(Y[2 * j3],     A0, A1, A2, A3, B0, B1);
                mma_f16(Y[2 * j3 + 1], A0, A1, A2, A3, B2, B3);
            }
        }
        // --- row 96 rank-1 update (fp32) ---
        {
            const float c0 = m0 * t96a;
            const float c1 = m1 * t96b;
            const __half2* w96 = reinterpret_cast<const __half2*>(
                curb + 96 * LDH + nbase + 2 * tig);
#pragma unroll
            for (int j = 0; j < 6; j++) {
                float2 w = __half22float2(w96[4 * j]);   // halfs offset 8j
                Y[j][0] += c0 * w.x;
                Y[j][1] += c0 * w.y;
                Y[j][2] += c1 * w.x;
                Y[j][3] += c1 * w.y;
            }
        }
    };

    // --- prefetch distance 3: 2 reg sets, 3 smem stages (R9-proven) ---
    float4 stgA[10], stgB[10];
    stage_ldg(stgA, W1, cstart, tid);                       // chunk 0
    if (ccnt > 1) stage_ldg(stgB, W1, cstart + 1, tid);     // chunk 1
    stage_sts(wb0, stgA, tid);                              // chunk 0 -> wb0
    if (ccnt > 2) stage_ldg(stgA, W1, cstart + 2, tid);     // chunk 2
    __syncthreads();

    __half *cur = wb0, *nxt = wb1, *spare = wb2;

    for (int ci = 0; ci < ccnt; ci += 2) {
        // even iter: compute chunk ci; stgB holds ci+1
        if (ci + 1 < ccnt) stage_sts(nxt, stgB, tid);
        if (ci + 3 < ccnt) stage_ldg(stgB, W1, cstart + ci + 3, tid);
        compute(cstart + ci, cur);
        __syncthreads();
        { __half* t = cur; cur = nxt; nxt = spare; spare = t; }

        // odd iter: compute chunk ci+1; stgA holds ci+2
        if (ci + 1 < ccnt) {
            if (ci + 2 < ccnt) stage_sts(nxt, stgA, tid);
            if (ci + 4 < ccnt) stage_ldg(stgA, W1, cstart + ci + 4, tid);
            compute(cstart + ci + 1, cur);
            __syncthreads();
            { __half* t = cur; cur = nxt; nxt = spare; spare = t; }
        }
    }

    // write fp32 partials [bk][b][h]
    float* dst = g_part + (size_t)bk * (BDIM * HDIM);
#pragma unroll
    for (int j = 0; j < 6; j++) {
        int h = nbase + 8 * j + 2 * tig;
        *reinterpret_cast<float2*>(dst + b0 * HDIM + h) =
            make_float2(Y[j][0], Y[j][1]);
        *reinterpret_cast<float2*>(dst + (b0 + 8) * HDIM + h) =
            make_float2(Y[j][2], Y[j][3]);
    }
}

// ---------------------------------------------------------------------------
// Kernel 3: reduce partials + bias/relu + W2 + heads. One block per batch row.
// ---------------------------------------------------------------------------
__global__ void __launch_bounds__(768) tfn_tail(
    const float* __restrict__ b1, const float* __restrict__ W2,
    const float* __restrict__ b2,
    const float* __restrict__ Wo1, const float* __restrict__ bo1,
    const float* __restrict__ Wo2, const float* __restrict__ bo2,
    const float* __restrict__ Wo3, const float* __restrict__ bo3,
    float* __restrict__ out) {
    __shared__ float ps[768];
    __shared__ float yr[HDIM];
    __shared__ float fs[HDIM];
    const int b   = blockIdx.x;
    const int tid = threadIdx.x;
    const int h   = tid % 96;
    const int g   = tid / 96;   // 0..7

    float acc = 0.f;
#pragma unroll 4
    for (int p = g; p < NBLK; p += 8)
        acc += g_part[(size_t)p * (BDIM * HDIM) + b * HDIM + h];
    ps[tid] = acc;
    __syncthreads();

    if (g == 0) {
        float r = b1[h];
#pragma unroll
        for (int i = 0; i < 8; i++) r += ps[h + 96 * i];
        yr[h] = fmaxf(r, 0.f);
    }
    __syncthreads();

    if (g == 0) {
        float f = b2[h];
#pragma unroll 8
        for (int k = 0; k < HDIM; k++) f += yr[k] * W2[k * HDIM + h];
        f = fmaxf(f, 0.f);
        fs[h] = f;
        out[b * HDIM + h] = f;
    }
    __syncthreads();

    if (tid < 6) {
        float a = bo1[tid];
        for (int k = 0; k < HDIM; k++) a += fs[k] * Wo1[k * 6 + tid];
        out[6144 + b * 6 + tid] = a;
    } else if (tid == 6) {
        float a = bo2[0];
        for (int k = 0; k < HDIM; k++) a += fs[k] * Wo2[k];
        out[6528 + b] = a;
    } else if (tid < 10) {
        int o = tid - 7;
        float a = bo3[o];
        for (int k = 0; k < HDIM; k++) a += fs[k] * Wo3[k * 3 + o];
        out[6592 + b * 3 + o] = a;
    }
    if (b == 0 && tid == 95) out[6784] = 0.f;  // interloss
}

// ---------------------------------------------------------------------------

extern "C" void kernel_launch(void* const* d_in, const int* in_sizes, int n_in,
                              void* d_out, int out_size) {
    (void)in_sizes; (void)n_in; (void)out_size;
    const float* audios = (const float*)d_in[0];
    const float* texts  = (const float*)d_in[1];
    const float* videos = (const float*)d_in[2];
    const float* Wa  = (const float*)d_in[3];
    const float* ba  = (const float*)d_in[4];
    const float* Wt  = (const float*)d_in[5];
    const float* bt  = (const float*)d_in[6];
    const float* Wv  = (const float*)d_in[7];
    const float* bv  = (const float*)d_in[8];
    const float* W1  = (const float*)d_in[9];
    const float* b1  = (const float*)d_in[10];
    const float* W2  = (const float*)d_in[11];
    const float* b2  = (const float*)d_in[12];
    const float* Wo1 = (const float*)d_in[13];
    const float* bo1 = (const float*)d_in[14];
    const float* Wo2 = (const float*)d_in[15];
    const float* bo2 = (const float*)d_in[16];
    const float* Wo3 = (const float*)d_in[17];
    const float* bo3 = (const float*)d_in[18];
    float* out = (float*)d_out;

    cudaFuncSetAttribute(tfn_main, cudaFuncAttributeMaxDynamicSharedMemorySize,
                         SMEM_BYTES);

    tfn_enc<<<dim3(64, 3), 768>>>(audios, texts, videos, Wa, ba, Wt, bt, Wv, bv);
    tfn_main<<<NBLK, 256, SMEM_BYTES>>>(W1);
    tfn_tail<<<64, 768>>>(b1, W2, b2, Wo1, bo1, Wo2, bo2, Wo3, bo3, out);
}

// round 14
// speedup vs baseline: 1.1065x; 1.1065x over previous
#include <cuda_runtime.h>
#include <cuda_fp16.h>
#include <cstdint>

// ---------------------------------------------------------------------------
// TFN forward. R14: fixes R13's staging index bug (48-col half-row = 12
// float4, not 6; 1164 float4 total, not 582). Same design: 2 independent
// CTAs per SM via N-split (48 cols each) so one CTA's compute fills the
// other's convoy stalls. grid 304, smem 63KB/CTA, launch_bounds(256,2).
// ---------------------------------------------------------------------------

#define NBLK   152
#define BDIM   64
#define HDIM   96
#define LDH2   56             // smem B row stride in halfs (112 B; 7x16B units,
                              // coprime with 8 -> LDSM conflict-free)
#define KR2    112            // 97 data rows + 15 zero rows (7 k16 steps)
#define WBUFH2 (KR2 * LDH2)   // 6272 halfs = 12544 B per stage
#define SMEM_BYTES (3*WBUFH2*2 + 6208*4 + 128*4)

__device__ float g_a1[BDIM * 97];
__device__ float g_v1[BDIM * 97];
__device__ float g_t1[BDIM * 97];
__device__ float g_part[NBLK * BDIM * HDIM];

// ---------------------------------------------------------------------------

__device__ __forceinline__ uint32_t h2u(__half2 h) {
    return *reinterpret_cast<uint32_t*>(&h);
}

__device__ __forceinline__ void mma_f16(float c[4],
                                        uint32_t a0, uint32_t a1,
                                        uint32_t a2, uint32_t a3,
                                        uint32_t b0, uint32_t b1) {
    asm volatile(
        "mma.sync.aligned.m16n8k16.row.col.f32.f16.f16.f32 "
        "{%0,%1,%2,%3}, {%4,%5,%6,%7}, {%8,%9}, {%0,%1,%2,%3};"
        : "+f"(c[0]), "+f"(c[1]), "+f"(c[2]), "+f"(c[3])
        : "r"(a0), "r"(a1), "r"(a2), "r"(a3), "r"(b0), "r"(b1));
}

struct __align__(8) H4 { __half2 a, b; };

// CTA loads its N-half of a chunk: 97 rows x 48 cols = 1164 float4.
// 256 threads: 4 each + 140 extra.
__device__ __forceinline__ void stage_ldg(float4 (&stg)[5],
                                          const float* __restrict__ W1,
                                          int av, int nh, int tid) {
    const float* src = W1 + (size_t)av * 9312 + nh * 48;
#pragma unroll
    for (int j = 0; j < 4; j++) {
        int q = tid + j * 256;
        int t = q / 12, c = (q - 12 * t) * 4;
        stg[j] = *reinterpret_cast<const float4*>(src + t * 96 + c);
    }
    if (tid < 140) {
        int q = tid + 1024;
        int t = q / 12, c = (q - 12 * t) * 4;
        stg[4] = *reinterpret_cast<const float4*>(src + t * 96 + c);
    }
}

__device__ __forceinline__ void cvt_store(__half* buf, int q, float4 v) {
    int t = q / 12;
    int c = (q - 12 * t) * 4;
    H4 o;
    o.a = __floats2half2_rn(v.x, v.y);
    o.b = __floats2half2_rn(v.z, v.w);
    *reinterpret_cast<H4*>(buf + t * LDH2 + c) = o;
}

__device__ __forceinline__ void stage_sts(__half* buf, const float4 (&stg)[5],
                                          int tid) {
#pragma unroll
    for (int j = 0; j < 4; j++) cvt_store(buf, tid + j * 256, stg[j]);
    if (tid < 140) cvt_store(buf, tid + 1024, stg[4]);
}

// ---------------------------------------------------------------------------
// Kernel 1: encoders. grid (64 batch, 3 mods), 768 threads = 96 h x 8 slices.
// ---------------------------------------------------------------------------
__global__ void __launch_bounds__(768) tfn_enc(
    const float* __restrict__ audios, const float* __restrict__ texts,
    const float* __restrict__ videos,
    const float* __restrict__ Wa, const float* __restrict__ ba,
    const float* __restrict__ Wt, const float* __restrict__ bt,
    const float* __restrict__ Wv, const float* __restrict__ bv) {
    const int b   = blockIdx.x;
    const int mod = blockIdx.y;
    const int tid = threadIdx.x;

    const float* x; const float* W; const float* bias; float* out; int K;
    if (mod == 0)      { x = audios; W = Wa; bias = ba; out = g_a1; K = 512; }
    else if (mod == 1) { x = texts;  W = Wt; bias = bt; out = g_t1; K = 1024; }
    else               { x = videos; W = Wv; bias = bv; out = g_v1; K = 512; }

    __shared__ float xs[1024];
    __shared__ float ps[768];

    const float* xb = x + (size_t)b * K;
    for (int i = tid; i < K; i += 768) xs[i] = xb[i];
    __syncthreads();

    const int h  = tid % 96;
    const int g  = tid / 96;           // 0..7
    const int kq = K >> 3;             // 64 or 128
    const int k0 = g * kq;

    float acc = 0.f;
#pragma unroll 8
    for (int k = k0; k < k0 + kq; k++)
        acc += xs[k] * W[k * HDIM + h];
    ps[tid] = acc;
    __syncthreads();

    if (g == 0) {
        float r = bias[h];
#pragma unroll
        for (int i = 0; i < 8; i++) r += ps[h + 96 * i];
        out[b * 97 + 1 + h] = fmaxf(r, 0.f);
        if (h == 0) out[b * 97] = 1.f;
    }
}

// ---------------------------------------------------------------------------
// Kernel 2: main fused trilinear GEMM. grid 304 = 152 chunk-ranges x 2 N-halves,
// 256 thr, 2 CTAs/SM. Prefetch distance 3 (2 reg sets, 3 smem stages).
// ---------------------------------------------------------------------------
__global__ void __launch_bounds__(256, 2) tfn_main(const float* __restrict__ W1) {
    extern __shared__ char smx[];
    __half* wb0 = reinterpret_cast<__half*>(smx);
    __half* wb1 = wb0 + WBUFH2;
    __half* wb2 = wb1 + WBUFH2;
    float*  v1s = reinterpret_cast<float*>(wb2 + WBUFH2);  // [64*97]
    float*  a1c = v1s + 6208;                              // [2*64]

    const int tid  = threadIdx.x;
    const int lane = tid & 31;
    const int wid  = tid >> 5;
    const int wm   = wid & 3;    // m-warp: batch rows 16*wm..16*wm+15
    const int wn   = wid >> 2;   // n-warp: 24-col block within the 48-col half
    const int gid  = lane >> 2;
    const int tig  = lane & 3;
    const int b0   = wm * 16 + gid;
    const int nbase = wn * 24;

    const int bk    = blockIdx.x;
    const int range = bk >> 1;
    const int nh    = bk & 1;
    // 9409 = 152*61 + 137 : first 137 ranges take 62 chunks
    const int cstart = (range < 137) ? range * 62 : range * 61 + 137;
    const int ccnt   = (range < 137) ? 62 : 61;
    const int caBase = cstart / 97;

    for (int i = tid; i < 6208; i += 256) v1s[i] = g_v1[i];
    if (tid < 128) {
        int b = tid & 63, col = tid >> 6;
        int ca = caBase + col; if (ca > 96) ca = 96;
        a1c[col * 64 + b] = g_a1[b * 97 + ca];
    }
    // zero rows 97..111 of all three stages (15*56 halfs = 420 u32 per stage)
    for (int i = tid; i < 3 * 420; i += 256) {
        int s = i / 420, r = i - s * 420;
        reinterpret_cast<uint32_t*>(wb0 + s * WBUFH2 + 97 * LDH2)[r] = 0;
    }

    // persistent t1 A-fragments as half2 pairs: 7 k16-steps (zero-padded)
    __half2 t1f[7][4];
#pragma unroll
    for (int ks = 0; ks < 7; ks++) {
        int ka = ks * 16 + 2 * tig;
        int kb = ka + 8;
        float x0 = (ka     < 97) ? g_t1[b0 * 97 + ka]           : 0.f;
        float x1 = (ka + 1 < 97) ? g_t1[b0 * 97 + ka + 1]       : 0.f;
        float y0 = (ka     < 97) ? g_t1[(b0 + 8) * 97 + ka]     : 0.f;
        float y1 = (ka + 1 < 97) ? g_t1[(b0 + 8) * 97 + ka + 1] : 0.f;
        float x2 = (kb     < 97) ? g_t1[b0 * 97 + kb]           : 0.f;
        float x3 = (kb + 1 < 97) ? g_t1[b0 * 97 + kb + 1]       : 0.f;
        float y2 = (kb     < 97) ? g_t1[(b0 + 8) * 97 + kb]     : 0.f;
        float y3 = (kb + 1 < 97) ? g_t1[(b0 + 8) * 97 + kb + 1] : 0.f;
        t1f[ks][0] = __floats2half2_rn(x0, x1);
        t1f[ks][1] = __floats2half2_rn(y0, y1);
        t1f[ks][2] = __floats2half2_rn(x2, x3);
        t1f[ks][3] = __floats2half2_rn(y2, y3);
    }

    float Y[3][4];
#pragma unroll
    for (int j = 0; j < 3; j++) { Y[j][0] = Y[j][1] = Y[j][2] = Y[j][3] = 0.f; }

    const int lrow = lane & 15;          // k row within k16 step
    const int lcol = (lane >> 4) * 8;    // 0 or 8 within n16 block

    auto compute = [&](int av, const __half* curb) {
        const int ca  = av / 97;
        const int cv  = av - ca * 97;
        const int cai = ca - caBase;
        const __half2 m0h = __float2half2_rn(a1c[cai * 64 + b0] * v1s[b0 * 97 + cv]);
        const __half2 m1h = __float2half2_rn(a1c[cai * 64 + b0 + 8] * v1s[(b0 + 8) * 97 + cv]);
#pragma unroll
        for (int ks = 0; ks < 7; ks++) {
            const uint32_t A0 = h2u(__hmul2(m0h, t1f[ks][0]));
            const uint32_t A1 = h2u(__hmul2(m1h, t1f[ks][1]));
            const uint32_t A2 = h2u(__hmul2(m0h, t1f[ks][2]));
            const uint32_t A3 = h2u(__hmul2(m1h, t1f[ks][3]));
            const __half* rowp = curb + (ks * 16 + lrow) * LDH2 + nbase;

            uint32_t s4 = (uint32_t)__cvta_generic_to_shared(rowp + lcol);
            uint32_t B0, B1, B2, B3;
            asm volatile(
                "ldmatrix.sync.aligned.m8n8.x4.trans.shared.b16 "
                "{%0,%1,%2,%3}, [%4];"
                : "=r"(B0), "=r"(B1), "=r"(B2), "=r"(B3) : "r"(s4));

            uint32_t s2 = (uint32_t)__cvta_generic_to_shared(rowp + 16);
            uint32_t C0, C1;
            asm volatile(
                "ldmatrix.sync.aligned.m8n8.x2.trans.shared.b16 "
                "{%0,%1}, [%2];"
                : "=r"(C0), "=r"(C1) : "r"(s2));

            mma_f16(Y[0], A0, A1, A2, A3, B0, B1);
            mma_f16(Y[1], A0, A1, A2, A3, B2, B3);
            mma_f16(Y[2], A0, A1, A2, A3, C0, C1);
        }
    };

    // --- prefetch distance 3: 2 reg sets, 3 smem stages ---
    float4 stgA[5], stgB[5];
    stage_ldg(stgA, W1, cstart, nh, tid);                       // chunk 0
    if (ccnt > 1) stage_ldg(stgB, W1, cstart + 1, nh, tid);     // chunk 1
    stage_sts(wb0, stgA, tid);                                  // chunk 0 -> wb0
    if (ccnt > 2) stage_ldg(stgA, W1, cstart + 2, nh, tid);     // chunk 2
    __syncthreads();

    __half *cur = wb0, *nxt = wb1, *spare = wb2;

    for (int ci = 0; ci < ccnt; ci += 2) {
        // even iter: compute chunk ci; stgB holds ci+1
        if (ci + 1 < ccnt) stage_sts(nxt, stgB, tid);
        if (ci + 3 < ccnt) stage_ldg(stgB, W1, cstart + ci + 3, nh, tid);
        compute(cstart + ci, cur);
        __syncthreads();
        { __half* t = cur; cur = nxt; nxt = spare; spare = t; }

        // odd iter: compute chunk ci+1; stgA holds ci+2
        if (ci + 1 < ccnt) {
            if (ci + 2 < ccnt) stage_sts(nxt, stgA, tid);
            if (ci + 4 < ccnt) stage_ldg(stgA, W1, cstart + ci + 4, nh, tid);
            compute(cstart + ci + 1, cur);
            __syncthreads();
            { __half* t = cur; cur = nxt; nxt = spare; spare = t; }
        }
    }

    // write fp32 partials [range][b][h], this CTA's 48-col half
    float* dst = g_part + (size_t)range * (BDIM * HDIM);
#pragma unroll
    for (int j = 0; j < 3; j++) {
        int h = nh * 48 + nbase + 8 * j + 2 * tig;
        *reinterpret_cast<float2*>(dst + b0 * HDIM + h) =
            make_float2(Y[j][0], Y[j][1]);
        *reinterpret_cast<float2*>(dst + (b0 + 8) * HDIM + h) =
            make_float2(Y[j][2], Y[j][3]);
    }
}

// ---------------------------------------------------------------------------
// Kernel 3: reduce partials + bias/relu + W2 + heads. One block per batch row.
// ---------------------------------------------------------------------------
__global__ void __launch_bounds__(768) tfn_tail(
    const float* __restrict__ b1, const float* __restrict__ W2,
    const float* __restrict__ b2,
    const float* __restrict__ Wo1, const float* __restrict__ bo1,
    const float* __restrict__ Wo2, const float* __restrict__ bo2,
    const float* __restrict__ Wo3, const float* __restrict__ bo3,
    float* __restrict__ out) {
    __shared__ float ps[768];
    __shared__ float yr[HDIM];
    __shared__ float fs[HDIM];
    const int b   = blockIdx.x;
    const int tid = threadIdx.x;
    const int h   = tid % 96;
    const int g   = tid / 96;   // 0..7

    float acc = 0.f;
#pragma unroll 4
    for (int p = g; p < NBLK; p += 8)
        acc += g_part[(size_t)p * (BDIM * HDIM) + b * HDIM + h];
    ps[tid] = acc;
    __syncthreads();

    if (g == 0) {
        float r = b1[h];
#pragma unroll
        for (int i = 0; i < 8; i++) r += ps[h + 96 * i];
        yr[h] = fmaxf(r, 0.f);
    }
    __syncthreads();

    if (g == 0) {
        float f = b2[h];
#pragma unroll 8
        for (int k = 0; k < HDIM; k++) f += yr[k] * W2[k * HDIM + h];
        f = fmaxf(f, 0.f);
        fs[h] = f;
        out[b * HDIM + h] = f;
    }
    __syncthreads();

    if (tid < 6) {
        float a = bo1[tid];
        for (int k = 0; k < HDIM; k++) a += fs[k] * Wo1[k * 6 + tid];
        out[6144 + b * 6 + tid] = a;
    } else if (tid == 6) {
        float a = bo2[0];
        for (int k = 0; k < HDIM; k++) a += fs[k] * Wo2[k];
        out[6528 + b] = a;
    } else if (tid < 10) {
        int o = tid - 7;
        float a = bo3[o];
        for (int k = 0; k < HDIM; k++) a += fs[k] * Wo3[k * 3 + o];
        out[6592 + b * 3 + o] = a;
    }
    if (b == 0 && tid == 95) out[6784] = 0.f;  // interloss
}

// ---------------------------------------------------------------------------

extern "C" void kernel_launch(void* const* d_in, const int* in_sizes, int n_in,
                              void* d_out, int out_size) {
    (void)in_sizes; (void)n_in; (void)out_size;
    const float* audios = (const float*)d_in[0];
    const float* texts  = (const float*)d_in[1];
    const float* videos = (const float*)d_in[2];
    const float* Wa  = (const float*)d_in[3];
    const float* ba  = (const float*)d_in[4];
    const float* Wt  = (const float*)d_in[5];
    const float* bt  = (const float*)d_in[6];
    const float* Wv  = (const float*)d_in[7];
    const float* bv  = (const float*)d_in[8];
    const float* W1  = (const float*)d_in[9];
    const float* b1  = (const float*)d_in[10];
    const float* W2  = (const float*)d_in[11];
    const float* b2  = (const float*)d_in[12];
    const float* Wo1 = (const float*)d_in[13];
    const float* bo1 = (const float*)d_in[14];
    const float* Wo2 = (const float*)d_in[15];
    const float* bo2 = (const float*)d_in[16];
    const float* Wo3 = (const float*)d_in[17];
    const float* bo3 = (const float*)d_in[18];
    float* out = (float*)d_out;

    cudaFuncSetAttribute(tfn_main, cudaFuncAttributeMaxDynamicSharedMemorySize,
                         SMEM_BYTES);

    tfn_enc<<<dim3(64, 3), 768>>>(audios, texts, videos, Wa, ba, Wt, bt, Wv, bv);
    tfn_main<<<2 * NBLK, 256, SMEM_BYTES>>>(W1);
    tfn_tail<<<64, 768>>>(b1, W2, b2, Wo1, bo1, Wo2, bo2, Wo3, bo3, out);
}

// round 15
// speedup vs baseline: 1.1270x; 1.0185x over previous
#include <cuda_runtime.h>
#include <cuda_fp16.h>
#include <cstdint>

// ---------------------------------------------------------------------------
// TFN forward. R15: main kernel = R14 verbatim (proven floor of the legacy-
// HMMA path after 6 neutral structural experiments). This round attacks the
// ~23us of latency-bound enc+tail by phase-splitting both:
//   enc_gemm (1024 blk partial GEMM) + enc_reduce (bias+relu)   13.2 -> ~3us
//   tail_a (512 blk partial reduce) + tail_b (finish+W2+heads)   9.5 -> ~3.5us
// ---------------------------------------------------------------------------

#define NBLK   152
#define BDIM   64
#define HDIM   96
#define LDH2   56             // smem B row stride in halfs (112 B)
#define KR2    112            // 97 data rows + 15 zero rows (7 k16 steps)
#define WBUFH2 (KR2 * LDH2)   // 6272 halfs = 12544 B per stage
#define SMEM_BYTES (3*WBUFH2*2 + 6208*4 + 128*4)

__device__ float g_a1[BDIM * 97];
__device__ float g_v1[BDIM * 97];
__device__ float g_t1[BDIM * 97];
__device__ float g_part[NBLK * BDIM * HDIM];
__device__ float g_epart[16 * BDIM * HDIM];   // enc k-slice partials
__device__ float g_ypart[8 * BDIM * HDIM];    // tail first-level partials

// ---------------------------------------------------------------------------

__device__ __forceinline__ uint32_t h2u(__half2 h) {
    return *reinterpret_cast<uint32_t*>(&h);
}

__device__ __forceinline__ void mma_f16(float c[4],
                                        uint32_t a0, uint32_t a1,
                                        uint32_t a2, uint32_t a3,
                                        uint32_t b0, uint32_t b1) {
    asm volatile(
        "mma.sync.aligned.m16n8k16.row.col.f32.f16.f16.f32 "
        "{%0,%1,%2,%3}, {%4,%5,%6,%7}, {%8,%9}, {%0,%1,%2,%3};"
        : "+f"(c[0]), "+f"(c[1]), "+f"(c[2]), "+f"(c[3])
        : "r"(a0), "r"(a1), "r"(a2), "r"(a3), "r"(b0), "r"(b1));
}

struct __align__(8) H4 { __half2 a, b; };

// CTA loads its N-half of a chunk: 97 rows x 48 cols = 1164 float4.
__device__ __forceinline__ void stage_ldg(float4 (&stg)[5],
                                          const float* __restrict__ W1,
                                          int av, int nh, int tid) {
    const float* src = W1 + (size_t)av * 9312 + nh * 48;
#pragma unroll
    for (int j = 0; j < 4; j++) {
        int q = tid + j * 256;
        int t = q / 12, c = (q - 12 * t) * 4;
        stg[j] = *reinterpret_cast<const float4*>(src + t * 96 + c);
    }
    if (tid < 140) {
        int q = tid + 1024;
        int t = q / 12, c = (q - 12 * t) * 4;
        stg[4] = *reinterpret_cast<const float4*>(src + t * 96 + c);
    }
}

__device__ __forceinline__ void cvt_store(__half* buf, int q, float4 v) {
    int t = q / 12;
    int c = (q - 12 * t) * 4;
    H4 o;
    o.a = __floats2half2_rn(v.x, v.y);
    o.b = __floats2half2_rn(v.z, v.w);
    *reinterpret_cast<H4*>(buf + t * LDH2 + c) = o;
}

__device__ __forceinline__ void stage_sts(__half* buf, const float4 (&stg)[5],
                                          int tid) {
#pragma unroll
    for (int j = 0; j < 4; j++) cvt_store(buf, tid + j * 256, stg[j]);
    if (tid < 140) cvt_store(buf, tid + 1024, stg[4]);
}

// ---------------------------------------------------------------------------
// Kernel 1a: enc partial GEMM. grid (64 b, 16 modslice), 192 thr = 96h x 2g.
// modslice: 0-3 audio, 4-11 text, 12-15 video; each covers 128 k.
// ---------------------------------------------------------------------------
__global__ void __launch_bounds__(192) tfn_enc_gemm(
    const float* __restrict__ audios, const float* __restrict__ texts,
    const float* __restrict__ videos,
    const float* __restrict__ Wa, const float* __restrict__ Wt,
    const float* __restrict__ Wv) {
    const int b   = blockIdx.x;
    const int ms  = blockIdx.y;
    const int tid = threadIdx.x;

    const float* x; const float* W; int K, k0;
    if (ms < 4)       { x = audios; W = Wa; K = 512;  k0 = ms * 128; }
    else if (ms < 12) { x = texts;  W = Wt; K = 1024; k0 = (ms - 4) * 128; }
    else              { x = videos; W = Wv; K = 512;  k0 = (ms - 12) * 128; }

    __shared__ float xs[128];
    __shared__ float ps[192];

    if (tid < 128) xs[tid] = x[(size_t)b * K + k0 + tid];
    __syncthreads();

    const int h = tid % 96;
    const int g = tid / 96;   // 0..1, 64 k each
    const float* Wp = W + (size_t)(k0 + g * 64) * HDIM + h;
    const float* xp = xs + g * 64;

    float acc = 0.f;
#pragma unroll 8
    for (int k = 0; k < 64; k++)
        acc += xp[k] * Wp[k * HDIM];
    ps[tid] = acc;
    __syncthreads();

    if (g == 0)
        g_epart[(ms * 64 + b) * HDIM + h] = ps[h] + ps[h + 96];
}

// ---------------------------------------------------------------------------
// Kernel 1b: enc reduce + bias + relu + ones column. grid (64, 3), 96 thr.
// ---------------------------------------------------------------------------
__global__ void __launch_bounds__(96) tfn_enc_reduce(
    const float* __restrict__ ba, const float* __restrict__ bt,
    const float* __restrict__ bv) {
    const int b   = blockIdx.x;
    const int mod = blockIdx.y;
    const int h   = threadIdx.x;

    const float* bias; float* out; int s0, s1;
    if (mod == 0)      { bias = ba; out = g_a1; s0 = 0;  s1 = 4; }
    else if (mod == 1) { bias = bt; out = g_t1; s0 = 4;  s1 = 12; }
    else               { bias = bv; out = g_v1; s0 = 12; s1 = 16; }

    float acc = bias[h];
#pragma unroll
    for (int s = s0; s < s1; s++)
        acc += g_epart[(s * 64 + b) * HDIM + h];
    out[b * 97 + 1 + h] = fmaxf(acc, 0.f);
    if (h == 0) out[b * 97] = 1.f;
}

// ---------------------------------------------------------------------------
// Kernel 2: main fused trilinear GEMM (R14 verbatim). grid 304, 256 thr,
// 2 CTAs/SM, prefetch distance 3.
// ---------------------------------------------------------------------------
__global__ void __launch_bounds__(256, 2) tfn_main(const float* __restrict__ W1) {
    extern __shared__ char smx[];
    __half* wb0 = reinterpret_cast<__half*>(smx);
    __half* wb1 = wb0 + WBUFH2;
    __half* wb2 = wb1 + WBUFH2;
    float*  v1s = reinterpret_cast<float*>(wb2 + WBUFH2);  // [64*97]
    float*  a1c = v1s + 6208;                              // [2*64]

    const int tid  = threadIdx.x;
    const int lane = tid & 31;
    const int wid  = tid >> 5;
    const int wm   = wid & 3;
    const int wn   = wid >> 2;
    const int gid  = lane >> 2;
    const int tig  = lane & 3;
    const int b0   = wm * 16 + gid;
    const int nbase = wn * 24;

    const int bk    = blockIdx.x;
    const int range = bk >> 1;
    const int nh    = bk & 1;
    const int cstart = (range < 137) ? range * 62 : range * 61 + 137;
    const int ccnt   = (range < 137) ? 62 : 61;
    const int caBase = cstart / 97;

    for (int i = tid; i < 6208; i += 256) v1s[i] = g_v1[i];
    if (tid < 128) {
        int b = tid & 63, col = tid >> 6;
        int ca = caBase + col; if (ca > 96) ca = 96;
        a1c[col * 64 + b] = g_a1[b * 97 + ca];
    }
    for (int i = tid; i < 3 * 420; i += 256) {
        int s = i / 420, r = i - s * 420;
        reinterpret_cast<uint32_t*>(wb0 + s * WBUFH2 + 97 * LDH2)[r] = 0;
    }

    __half2 t1f[7][4];
#pragma unroll
    for (int ks = 0; ks < 7; ks++) {
        int ka = ks * 16 + 2 * tig;
        int kb = ka + 8;
        float x0 = (ka     < 97) ? g_t1[b0 * 97 + ka]           : 0.f;
        float x1 = (ka + 1 < 97) ? g_t1[b0 * 97 + ka + 1]       : 0.f;
        float y0 = (ka     < 97) ? g_t1[(b0 + 8) * 97 + ka]     : 0.f;
        float y1 = (ka + 1 < 97) ? g_t1[(b0 + 8) * 97 + ka + 1] : 0.f;
        float x2 = (kb     < 97) ? g_t1[b0 * 97 + kb]           : 0.f;
        float x3 = (kb + 1 < 97) ? g_t1[b0 * 97 + kb + 1]       : 0.f;
        float y2 = (kb     < 97) ? g_t1[(b0 + 8) * 97 + kb]     : 0.f;
        float y3 = (kb + 1 < 97) ? g_t1[(b0 + 8) * 97 + kb + 1] : 0.f;
        t1f[ks][0] = __floats2half2_rn(x0, x1);
        t1f[ks][1] = __floats2half2_rn(y0, y1);
        t1f[ks][2] = __floats2half2_rn(x2, x3);
        t1f[ks][3] = __floats2half2_rn(y2, y3);
    }

    float Y[3][4];
#pragma unroll
    for (int j = 0; j < 3; j++) { Y[j][0] = Y[j][1] = Y[j][2] = Y[j][3] = 0.f; }

    const int lrow = lane & 15;
    const int lcol = (lane >> 4) * 8;

    auto compute = [&](int av, const __half* curb) {
        const int ca  = av / 97;
        const int cv  = av - ca * 97;
        const int cai = ca - caBase;
        const __half2 m0h = __float2half2_rn(a1c[cai * 64 + b0] * v1s[b0 * 97 + cv]);
        const __half2 m1h = __float2half2_rn(a1c[cai * 64 + b0 + 8] * v1s[(b0 + 8) * 97 + cv]);
#pragma unroll
        for (int ks = 0; ks < 7; ks++) {
            const uint32_t A0 = h2u(__hmul2(m0h, t1f[ks][0]));
            const uint32_t A1 = h2u(__hmul2(m1h, t1f[ks][1]));
            const uint32_t A2 = h2u(__hmul2(m0h, t1f[ks][2]));
            const uint32_t A3 = h2u(__hmul2(m1h, t1f[ks][3]));
            const __half* rowp = curb + (ks * 16 + lrow) * LDH2 + nbase;

            uint32_t s4 = (uint32_t)__cvta_generic_to_shared(rowp + lcol);
            uint32_t B0, B1, B2, B3;
            asm volatile(
                "ldmatrix.sync.aligned.m8n8.x4.trans.shared.b16 "
                "{%0,%1,%2,%3}, [%4];"
                : "=r"(B0), "=r"(B1), "=r"(B2), "=r"(B3) : "r"(s4));

            uint32_t s2 = (uint32_t)__cvta_generic_to_shared(rowp + 16);
            uint32_t C0, C1;
            asm volatile(
                "ldmatrix.sync.aligned.m8n8.x2.trans.shared.b16 "
                "{%0,%1}, [%2];"
                : "=r"(C0), "=r"(C1) : "r"(s2));

            mma_f16(Y[0], A0, A1, A2, A3, B0, B1);
            mma_f16(Y[1], A0, A1, A2, A3, B2, B3);
            mma_f16(Y[2], A0, A1, A2, A3, C0, C1);
        }
    };

    float4 stgA[5], stgB[5];
    stage_ldg(stgA, W1, cstart, nh, tid);
    if (ccnt > 1) stage_ldg(stgB, W1, cstart + 1, nh, tid);
    stage_sts(wb0, stgA, tid);
    if (ccnt > 2) stage_ldg(stgA, W1, cstart + 2, nh, tid);
    __syncthreads();

    __half *cur = wb0, *nxt = wb1, *spare = wb2;

    for (int ci = 0; ci < ccnt; ci += 2) {
        if (ci + 1 < ccnt) stage_sts(nxt, stgB, tid);
        if (ci + 3 < ccnt) stage_ldg(stgB, W1, cstart + ci + 3, nh, tid);
        compute(cstart + ci, cur);
        __syncthreads();
        { __half* t = cur; cur = nxt; nxt = spare; spare = t; }

        if (ci + 1 < ccnt) {
            if (ci + 2 < ccnt) stage_sts(nxt, stgA, tid);
            if (ci + 4 < ccnt) stage_ldg(stgA, W1, cstart + ci + 4, nh, tid);
            compute(cstart + ci + 1, cur);
            __syncthreads();
            { __half* t = cur; cur = nxt; nxt = spare; spare = t; }
        }
    }

    float* dst = g_part + (size_t)range * (BDIM * HDIM);
#pragma unroll
    for (int j = 0; j < 3; j++) {
        int h = nh * 48 + nbase + 8 * j + 2 * tig;
        *reinterpret_cast<float2*>(dst + b0 * HDIM + h) =
            make_float2(Y[j][0], Y[j][1]);
        *reinterpret_cast<float2*>(dst + (b0 + 8) * HDIM + h) =
            make_float2(Y[j][2], Y[j][3]);
    }
}

// ---------------------------------------------------------------------------
// Kernel 3a: first-level partial reduce. grid (64 b, 8 pg), 96 thr.
// Each thread sums 19 of the 152 partials for one (b,h).
// ---------------------------------------------------------------------------
__global__ void __launch_bounds__(96) tfn_tail_a() {
    const int b  = blockIdx.x;
    const int pg = blockIdx.y;
    const int h  = threadIdx.x;

    float acc = 0.f;
#pragma unroll
    for (int p = pg; p < NBLK; p += 8)
        acc += g_part[(size_t)p * (BDIM * HDIM) + b * HDIM + h];
    g_ypart[(pg * 64 + b) * HDIM + h] = acc;
}

// ---------------------------------------------------------------------------
// Kernel 3b: finish y1 + W2 + heads. grid 64, 384 thr = 96h x 4g.
// ---------------------------------------------------------------------------
__global__ void __launch_bounds__(384) tfn_tail_b(
    const float* __restrict__ b1, const float* __restrict__ W2,
    const float* __restrict__ b2,
    const float* __restrict__ Wo1, const float* __restrict__ bo1,
    const float* __restrict__ Wo2, const float* __restrict__ bo2,
    const float* __restrict__ Wo3, const float* __restrict__ bo3,
    float* __restrict__ out) {
    __shared__ float yr[HDIM];
    __shared__ float ps[384];
    __shared__ float fs[HDIM];
    const int b   = blockIdx.x;
    const int tid = threadIdx.x;
    const int h   = tid % 96;
    const int g   = tid / 96;   // 0..3

    if (g == 0) {
        float r = b1[h];
#pragma unroll
        for (int pg = 0; pg < 8; pg++)
            r += g_ypart[(pg * 64 + b) * HDIM + h];
        yr[h] = fmaxf(r, 0.f);
    }
    __syncthreads();

    // W2: 4-way k-split
    {
        float acc = 0.f;
        const int k0 = g * 24;
#pragma unroll
        for (int k = 0; k < 24; k++)
            acc += yr[k0 + k] * W2[(k0 + k) * HDIM + h];
        ps[tid] = acc;
    }
    __syncthreads();

    if (g == 0) {
        float f = b2[h] + ((ps[h] + ps[h + 96]) + (ps[h + 192] + ps[h + 288]));
        f = fmaxf(f, 0.f);
        fs[h] = f;
        out[b * HDIM + h] = f;
    }
    __syncthreads();

    if (tid < 6) {
        float a = bo1[tid];
        for (int k = 0; k < HDIM; k++) a += fs[k] * Wo1[k * 6 + tid];
        out[6144 + b * 6 + tid] = a;
    } else if (tid == 6) {
        float a = bo2[0];
        for (int k = 0; k < HDIM; k++) a += fs[k] * Wo2[k];
        out[6528 + b] = a;
    } else if (tid < 10) {
        int o = tid - 7;
        float a = bo3[o];
        for (int k = 0; k < HDIM; k++) a += fs[k] * Wo3[k * 3 + o];
        out[6592 + b * 3 + o] = a;
    }
    if (b == 0 && tid == 95) out[6784] = 0.f;  // interloss
}

// ---------------------------------------------------------------------------

extern "C" void kernel_launch(void* const* d_in, const int* in_sizes, int n_in,
                              void* d_out, int out_size) {
    (void)in_sizes; (void)n_in; (void)out_size;
    const float* audios = (const float*)d_in[0];
    const float* texts  = (const float*)d_in[1];
    const float* videos = (const float*)d_in[2];
    const float* Wa  = (const float*)d_in[3];
    const float* ba  = (const float*)d_in[4];
    const float* Wt  = (const float*)d_in[5];
    const float* bt  = (const float*)d_in[6];
    const float* Wv  = (const float*)d_in[7];
    const float* bv  = (const float*)d_in[8];
    const float* W1  = (const float*)d_in[9];
    const float* b1  = (const float*)d_in[10];
    const float* W2  = (const float*)d_in[11];
    const float* b2  = (const float*)d_in[12];
    const float* Wo1 = (const float*)d_in[13];
    const float* bo1 = (const float*)d_in[14];
    const float* Wo2 = (const float*)d_in[15];
    const float* bo2 = (const float*)d_in[16];
    const float* Wo3 = (const float*)d_in[17];
    const float* bo3 = (const float*)d_in[18];
    float* out = (float*)d_out;

    cudaFuncSetAttribute(tfn_main, cudaFuncAttributeMaxDynamicSharedMemorySize,
                         SMEM_BYTES);

    tfn_enc_gemm<<<dim3(64, 16), 192>>>(audios, texts, videos, Wa, Wt, Wv);
    tfn_enc_reduce<<<dim3(64, 3), 96>>>(ba, bt, bv);
    tfn_main<<<2 * NBLK, 256, SMEM_BYTES>>>(W1);
    tfn_tail_a<<<dim3(64, 8), 96>>>();
    tfn_tail_b<<<64, 384>>>(b1, W2, b2, Wo1, bo1, Wo2, bo2, Wo3, bo3, out);
}